// round 13
// baseline (speedup 1.0000x reference)
#include <cuda_runtime.h>
#include <math.h>

#define Nn 512
#define Bb 8
#define Cc 64
#define Hh 64
#define Tt 16
#define Ll 2
#define Ee 16384
#define NB (Nn*Bb)          /* 4096 rows for gate GEMMs */
#define MAT (NB*Hh)         /* 262144 floats per [N,B,H] matrix */
#define NCTAS 128
#define NTHREADS 512

typedef unsigned long long u64;

// ---------------- device scratch ----------------
__device__ float g_deg[Nn];
__device__ float g_dinv[Nn];
__device__ int   g_cnt[Nn];
__device__ int   g_fill[Nn];
__device__ int   g_rowptr[Nn + 1];
__device__ int   g_col[Ee];
__device__ float g_val[Ee];
__device__ float g_U[(long)Tt*3*MAT];
__device__ float g_Xc[(long)Tt*Ll*3*MAT];
__device__ float g_h[MAT];
__device__ float g_z[MAT];
__device__ float g_hr[MAT];
__device__ float g_T1[MAT];
__device__ float g_T2[MAT];
__device__ float g_sp[MAT];
__device__ float g_tp[MAT];
__device__ int   g_idx32;
__device__ unsigned g_cnt2[2] = {0u, 0u};  // ping-pong arrival counters (0 at launch/exit)
__device__ unsigned g_barPhase = 0;        // monotonic across launches (wrap-safe)

// ---------------- f32x2 helpers ----------------
__device__ __forceinline__ u64 ffma2(u64 a, u64 b, u64 c) {
    u64 d;
    asm("fma.rn.f32x2 %0, %1, %2, %3;" : "=l"(d) : "l"(a), "l"(b), "l"(c));
    return d;
}
__device__ __forceinline__ u64 splat2(float x) {
    u64 r;
    asm("mov.b64 %0, {%1, %1};" : "=l"(r) : "r"(__float_as_uint(x)));
    return r;
}
__device__ __forceinline__ float2 u2f(u64 v) {
    float2 f;
    asm("mov.b64 {%0, %1}, %2;" : "=f"(f.x), "=f"(f.y) : "l"(v));
    return f;
}

// ---------------- grid barrier v2: red-arrive + CTA0 aggregate ----------------
__device__ __forceinline__ unsigned ld_acq(unsigned* p) {
    unsigned v;
    asm volatile("ld.acquire.gpu.u32 %0, [%1];" : "=r"(v) : "l"(p) : "memory");
    return v;
}
__device__ __forceinline__ void st_rel(unsigned* p, unsigned v) {
    asm volatile("st.release.gpu.u32 [%0], %1;" :: "l"(p), "r"(v) : "memory");
}
__device__ __forceinline__ void red_add_rel(unsigned* p, unsigned v) {
    asm volatile("red.release.gpu.global.add.u32 [%0], %1;" :: "l"(p), "r"(v) : "memory");
}
// bph: absolute monotonic phase target (tid0-only state, seeded from g_barPhase at entry)
__device__ __forceinline__ void grid_bar(unsigned& bph) {
    __syncthreads();
    if (threadIdx.x == 0) {
        bph += 1;
        unsigned slot = bph & 1u;
        red_add_rel(&g_cnt2[slot], 1u);
        if (blockIdx.x == 0) {
            while (ld_acq(&g_cnt2[slot]) < NCTAS) { }
            g_cnt2[slot] = 0;            // reset before release; ordered by release below
            st_rel(&g_barPhase, bph);
        } else {
            while ((int)(ld_acq(&g_barPhase) - bph) < 0) { }
        }
    }
    __syncthreads();
}

// ---------------- shared memory ----------------
struct SmemP {
    float sps[64][65];
    float tps[32][65];
    float w2[64];
};
union SmemBuf {
    float Ws[192 * 64];   // 48KB weight tile (row-streamed GEMMs)
    SmemP p;
};
#define SMEM_BYTES (sizeof(SmemBuf))

__device__ __forceinline__ int load_idx(const void* ei, long i) {
    if (g_idx32) return ((const int*)ei)[i];
    return (int)(((const long long*)ei)[i]);
}

// ============ SPARSE S-apply: dst[n][c] = alpha * sum_nnz w * X[k][c] (+ beta*Y) ============
__device__ __forceinline__ void sparse_apply(
        float* dst, const float* X, const float* Y, float alpha, float beta) {
    int gw   = blockIdx.x * (NTHREADS / 32) + (threadIdx.x >> 5);  // 0..2047
    int lane = threadIdx.x & 31;
    int node = gw >> 2;
    int c0   = ((gw & 3) << 7) + lane * 4;
    int rp0 = g_rowptr[node], rp1 = g_rowptr[node + 1];

    float ax = 0.f, ay = 0.f, az = 0.f, aw = 0.f;
    int i = rp0;
    for (; i + 4 <= rp1; i += 4) {
        int   k0 = g_col[i],   k1 = g_col[i+1], k2 = g_col[i+2], k3 = g_col[i+3];
        float w0 = g_val[i],   w1 = g_val[i+1], w2 = g_val[i+2], w3 = g_val[i+3];
        float4 x0 = *(const float4*)&X[(long)k0 * 512 + c0];
        float4 x1 = *(const float4*)&X[(long)k1 * 512 + c0];
        float4 x2 = *(const float4*)&X[(long)k2 * 512 + c0];
        float4 x3 = *(const float4*)&X[(long)k3 * 512 + c0];
        ax = fmaf(w0, x0.x, ax); ay = fmaf(w0, x0.y, ay); az = fmaf(w0, x0.z, az); aw = fmaf(w0, x0.w, aw);
        ax = fmaf(w1, x1.x, ax); ay = fmaf(w1, x1.y, ay); az = fmaf(w1, x1.z, az); aw = fmaf(w1, x1.w, aw);
        ax = fmaf(w2, x2.x, ax); ay = fmaf(w2, x2.y, ay); az = fmaf(w2, x2.z, az); aw = fmaf(w2, x2.w, aw);
        ax = fmaf(w3, x3.x, ax); ay = fmaf(w3, x3.y, ay); az = fmaf(w3, x3.z, az); aw = fmaf(w3, x3.w, aw);
    }
    for (; i < rp1; i++) {
        int k = g_col[i]; float w = g_val[i];
        float4 xv = *(const float4*)&X[(long)k * 512 + c0];
        ax = fmaf(w, xv.x, ax); ay = fmaf(w, xv.y, ay);
        az = fmaf(w, xv.z, az); aw = fmaf(w, xv.w, aw);
    }
    long off = (long)node * 512 + c0;
    float4 o;
    o.x = alpha * ax; o.y = alpha * ay; o.z = alpha * az; o.w = alpha * aw;
    if (Y) {
        float4 y = *(const float4*)&Y[off];
        o.x += beta * y.x; o.y += beta * y.y; o.z += beta * y.z; o.w += beta * y.w;
    }
    *(float4*)&dst[off] = o;
}

// ============ W loader: Wg (nrows x 64 row-major, contiguous) -> smem ============
__device__ __forceinline__ void load_W(float* Ws, const float* Wg, int nrows) {
    __syncthreads();   // prior readers of Ws done
    int n = nrows * 64;
    for (int i = threadIdx.x * 4; i < n; i += NTHREADS * 4)
        *(float4*)&Ws[i] = *(const float4*)&Wg[i];
    __syncthreads();
}

// ============ row-streaming GEMM cores: thread owns 1 row x CW cols ============
// acc over k = 0..nk64*64-1; A source p = k/64 from mats[], W from smem Ws[k][c0..]
__device__ __forceinline__ void mac8(u64* acc, u64 a, const float* w) {
    ulonglong2 w0 = *(const ulonglong2*)w;
    ulonglong2 w1 = *(const ulonglong2*)(w + 4);
    acc[0] = ffma2(a, w0.x, acc[0]); acc[1] = ffma2(a, w0.y, acc[1]);
    acc[2] = ffma2(a, w1.x, acc[2]); acc[3] = ffma2(a, w1.y, acc[3]);
}
__device__ __forceinline__ void mac4(u64* acc, u64 a, const float* w) {
    ulonglong2 w0 = *(const ulonglong2*)w;
    acc[0] = ffma2(a, w0.x, acc[0]); acc[1] = ffma2(a, w0.y, acc[1]);
}

__device__ __forceinline__ void row_stream8(
        const float* Ws, const float* A0, const float* A1, const float* A2,
        int nk64, int row, int c0, u64* acc) {
    const float* mats[3] = {A0, A1, A2};
    for (int p = 0; p < nk64; p++) {
        const float* Arow = mats[p] + (long)row * 64;
        const float* wp = Ws + (p * 64) * 64 + c0;
        #pragma unroll 4
        for (int q = 0; q < 16; q++) {
            float4 av = *(const float4*)&Arow[q * 4];
            const float* wb = wp + (q * 4) * 64;
            mac8(acc, splat2(av.x), wb + 0 * 64);
            mac8(acc, splat2(av.y), wb + 1 * 64);
            mac8(acc, splat2(av.z), wb + 2 * 64);
            mac8(acc, splat2(av.w), wb + 3 * 64);
        }
    }
}
__device__ __forceinline__ void row_stream4(
        const float* Ws, const float* A0, const float* A1, const float* A2,
        int nk64, int row, int c0, u64* acc) {
    const float* mats[3] = {A0, A1, A2};
    for (int p = 0; p < nk64; p++) {
        const float* Arow = mats[p] + (long)row * 64;
        const float* wp = Ws + (p * 64) * 64 + c0;
        #pragma unroll 4
        for (int q = 0; q < 16; q++) {
            float4 av = *(const float4*)&Arow[q * 4];
            const float* wb = wp + (q * 4) * 64;
            mac4(acc, splat2(av.x), wb + 0 * 64);
            mac4(acc, splat2(av.y), wb + 1 * 64);
            mac4(acc, splat2(av.z), wb + 2 * 64);
            mac4(acc, splat2(av.w), wb + 3 * 64);
        }
    }
}

// predict one 64(s) x 32(t) tile for batch b, 512 threads, 4 outputs each
__device__ __forceinline__ void predict_tile(
        SmemP& s, int b, int sBase, int tBase,
        const float* b1, const float* W2,
        const float* b2, float* out) {
    int tid = threadIdx.x;
    __syncthreads();
    #pragma unroll
    for (int i = tid; i < 4096; i += NTHREADS) {
        int r = i >> 6, cc = i & 63;
        s.sps[r][cc] = g_sp[((long)(sBase + r) * Bb + b) * Hh + cc] + b1[cc];
    }
    #pragma unroll
    for (int i = tid; i < 2048; i += NTHREADS) {
        int r = i >> 6, cc = i & 63;
        s.tps[r][cc] = g_tp[((long)(tBase + r) * Bb + b) * Hh + cc];
    }
    if (tid < 64) s.w2[tid] = W2[tid];
    __syncthreads();

    int tx = tid & 31, ty = tid >> 5;
    float bias = b2[0];
    float a0 = bias, a1 = bias, a2 = bias, a3 = bias;
    #pragma unroll
    for (int hh = 0; hh < 64; hh++) {
        float tv = s.tps[tx][hh];
        float w  = s.w2[hh];
        a0 += fmaxf(s.sps[ty +  0][hh] + tv, 0.0f) * w;
        a1 += fmaxf(s.sps[ty + 16][hh] + tv, 0.0f) * w;
        a2 += fmaxf(s.sps[ty + 32][hh] + tv, 0.0f) * w;
        a3 += fmaxf(s.sps[ty + 48][hh] + tv, 0.0f) * w;
    }
    long colBase = (long)b * Nn * Nn + (long)tBase + tx;
    out[colBase + (long)(sBase + ty +  0) * Nn] = a0;
    out[colBase + (long)(sBase + ty + 16) * Nn] = a1;
    out[colBase + (long)(sBase + ty + 32) * Nn] = a2;
    out[colBase + (long)(sBase + ty + 48) * Nn] = a3;
}

// ============ THE ONLY KERNEL: 128 CTAs x 512 threads, persistent ============
__global__ __launch_bounds__(NTHREADS, 1) void mega_kernel(
        const float* x, const float* ew,
        const float* Wx, const float* bx,
        const float* Wh, const float* bh,
        const float* W1, const float* b1,
        const float* W2, const float* b2,
        const void*  ei,
        float* out) {
    extern __shared__ __align__(16) char smraw[];
    float* Ws = ((SmemBuf*)smraw)->Ws;
    SmemP& smp = ((SmemBuf*)smraw)->p;

    const int c = blockIdx.x;
    const int tid = threadIdx.x;
    const long gtid = (long)c * NTHREADS + tid;   // 0..65535
    unsigned bph = 0;
    if (tid == 0) bph = ld_acq(&g_barPhase);

    // ---- Phase 0a: probe + zero ----
    if (c == 0 && tid == 0) {
        const long long* p = (const long long*)ei;
        int is64 = 1;
        for (int i = 0; i < 64; i++) {
            long long v = p[i];
            if (v < 0 || v >= (long long)Nn) { is64 = 0; break; }
        }
        g_idx32 = is64 ? 0 : 1;
    }
    {
        float4 zz = make_float4(0.f, 0.f, 0.f, 0.f);
        *(float4*)&g_h[gtid * 4] = zz;
        if (gtid < Nn) { g_deg[gtid] = 0.0f; g_cnt[gtid] = 0; g_fill[gtid] = 0; }
    }
    grid_bar(bph);

    // ---- Phase 0b: degree + per-dst counts ----
    if (gtid < Ee) {
        int s = load_idx(ei, gtid);
        int d = load_idx(ei, (long)Ee + gtid);
        atomicAdd(&g_deg[s], ew[gtid]);
        atomicAdd(&g_cnt[d], 1);
    }
    grid_bar(bph);

    // ---- Phase 0c: dinv + CSR rowptr scan ----
    if (gtid < Nn) {
        float d = g_deg[gtid];
        g_dinv[gtid] = (d > 0.0f) ? rsqrtf(fmaxf(d, 1e-12f)) : 0.0f;
    }
    if (c == 0 && tid == 0) {
        int acc = 0;
        for (int i = 0; i < Nn; i++) { g_rowptr[i] = acc; acc += g_cnt[i]; }
        g_rowptr[Nn] = acc;
    }
    grid_bar(bph);

    // ---- Phase 0d: CSR fill ----
    if (gtid < Ee) {
        int s = load_idx(ei, gtid);
        int d = load_idx(ei, (long)Ee + gtid);
        int slot = atomicAdd(&g_fill[d], 1);
        int idx = g_rowptr[d] + slot;
        g_col[idx] = s;
        g_val[idx] = -ew[gtid] * g_dinv[s] * g_dinv[d];
    }
    grid_bar(bph);

    // ---- Phase A: permute x -> U0, all CTAs (4,194,304 / 128 = 32768 per CTA) ----
    {
        long base = (long)c * 32768;
        for (long i = base + tid; i < base + 32768; i += NTHREADS) {
            int cc = (int)(i & 63);
            long r = i >> 6;
            int n = (int)(r % Nn); r /= Nn;
            int t = (int)(r % Tt);
            int b = (int)(r / Tt);
            g_U[((long)(t*3) * NB + (long)n * Bb + b) * Hh + cc] = x[i];
        }
    }
    grid_bar(bph);

    // ---- Phase B: x-basis via sparse S ----
    for (int t = 0; t < Tt; t++)
        sparse_apply(g_U + (long)(t*3+1)*MAT, g_U + (long)(t*3)*MAT, (const float*)0, 1.0f, 0.0f);
    grid_bar(bph);
    for (int t = 0; t < Tt; t++)
        sparse_apply(g_U + (long)(t*3+2)*MAT, g_U + (long)(t*3+1)*MAT, g_U + (long)(t*3)*MAT, 2.0f, -1.0f);
    grid_bar(bph);

    // ---- Phase C: Xc[t][lg] = sum_k U[t][k] @ Wx[lg][k] + bx + bh ----
    // 6 lg x 64 row-tiles = 384 units over 128 CTAs (3 each); W reused across all 16 t.
    for (int j = 0; j < 3; j++) {
        int unit = c + NCTAS * j;          // 0..383
        int lg = unit >> 6;                // 0..5
        int rowBase = (unit & 63) * 64;
        load_W(Ws, Wx + (long)lg * 3 * 4096, 192);
        int row = rowBase + (tid >> 3);
        int c0  = (tid & 7) * 8;
        float bsum[8];
        #pragma unroll
        for (int i = 0; i < 8; i++)
            bsum[i] = bx[lg*Hh + c0 + i] + bh[lg*Hh + c0 + i];
        float* obase = g_Xc + ((long)(lg/3) * 3 + (lg % 3)) * MAT;   // + t*2*3*MAT below
        for (int t = 0; t < Tt; t++) {
            u64 acc[4] = {0ull,0ull,0ull,0ull};
            row_stream8(Ws,
                        g_U + (long)(t*3 + 0) * MAT,
                        g_U + (long)(t*3 + 1) * MAT,
                        g_U + (long)(t*3 + 2) * MAT,
                        3, row, c0, acc);
            float* o = obase + (long)t * Ll * 3 * MAT;
            long off = (long)row * 64 + c0;
            float2 f0 = u2f(acc[0]), f1 = u2f(acc[1]), f2 = u2f(acc[2]), f3 = u2f(acc[3]);
            float4 v0, v1;
            v0.x = f0.x + bsum[0]; v0.y = f0.y + bsum[1];
            v0.z = f1.x + bsum[2]; v0.w = f1.y + bsum[3];
            v1.x = f2.x + bsum[4]; v1.y = f2.y + bsum[5];
            v1.z = f3.x + bsum[6]; v1.w = f3.y + bsum[7];
            *(float4*)&o[off] = v0;
            *(float4*)&o[off + 4] = v1;
        }
    }
    grid_bar(bph);

    // ---- Phase D: recurrent chain, 32 cells x 6 stages ----
    for (int cell = 0; cell < Tt * Ll; cell++) {
        int t = cell >> 1, l = cell & 1;
        const float* Wl    = Wh + (long)l * 9 * (Hh*Hh);
        const float* Xc_tl = g_Xc + ((long)(t*Ll + l) * 3) * MAT;

        // prefetch this CTA's gate W (z for c<64, r for c>=64) behind the sparse stages
        int g = c >> 6;
        load_W(Ws, Wl + (long)g * 3 * 4096, 192);

        // stage 1: T1 = S @ h
        sparse_apply(g_T1, g_h, (const float*)0, 1.0f, 0.0f);
        grid_bar(bph);
        // stage 2: T2 = 2 S @ T1 - h
        sparse_apply(g_T2, g_T1, g_h, 2.0f, -1.0f);
        grid_bar(bph);

        // stage 3: gates z (c<64) / r->hr (c>=64); 64 rows x 64 cols per CTA
        {
            int row = (c & 63) * 64 + (tid >> 3);
            int c0  = (tid & 7) * 8;
            u64 acc[4] = {0ull,0ull,0ull,0ull};
            row_stream8(Ws, g_h, g_T1, g_T2, 3, row, c0, acc);
            const float* Xc = Xc_tl + (long)g * MAT;
            long off = (long)row * 64 + c0;
            float4 xc0 = *(const float4*)&Xc[off];
            float4 xc1 = *(const float4*)&Xc[off + 4];
            float2 f0 = u2f(acc[0]), f1 = u2f(acc[1]), f2 = u2f(acc[2]), f3 = u2f(acc[3]);
            float v[8] = { f0.x + xc0.x, f0.y + xc0.y, f1.x + xc0.z, f1.y + xc0.w,
                           f2.x + xc1.x, f2.y + xc1.y, f3.x + xc1.z, f3.y + xc1.w };
            if (g == 0) {
                float4 o0, o1;
                o0.x = 1.0f/(1.0f+expf(-v[0])); o0.y = 1.0f/(1.0f+expf(-v[1]));
                o0.z = 1.0f/(1.0f+expf(-v[2])); o0.w = 1.0f/(1.0f+expf(-v[3]));
                o1.x = 1.0f/(1.0f+expf(-v[4])); o1.y = 1.0f/(1.0f+expf(-v[5]));
                o1.z = 1.0f/(1.0f+expf(-v[6])); o1.w = 1.0f/(1.0f+expf(-v[7]));
                *(float4*)&g_z[off] = o0; *(float4*)&g_z[off + 4] = o1;
            } else {
                float4 h0 = *(const float4*)&g_h[off];
                float4 h1 = *(const float4*)&g_h[off + 4];
                float4 o0, o1;
                o0.x = h0.x/(1.0f+expf(-v[0])); o0.y = h0.y/(1.0f+expf(-v[1]));
                o0.z = h0.z/(1.0f+expf(-v[2])); o0.w = h0.w/(1.0f+expf(-v[3]));
                o1.x = h1.x/(1.0f+expf(-v[4])); o1.y = h1.y/(1.0f+expf(-v[5]));
                o1.z = h1.z/(1.0f+expf(-v[6])); o1.w = h1.w/(1.0f+expf(-v[7]));
                *(float4*)&g_hr[off] = o0; *(float4*)&g_hr[off + 4] = o1;
            }
        }
        grid_bar(bph);

        // prefetch h~ gate W behind the next sparse stages
        load_W(Ws, Wl + (long)2 * 3 * 4096, 192);

        // stage 4: T1 = S @ hr
        sparse_apply(g_T1, g_hr, (const float*)0, 1.0f, 0.0f);
        grid_bar(bph);
        // stage 5: T2 = 2 S @ T1 - hr
        sparse_apply(g_T2, g_T1, g_hr, 2.0f, -1.0f);
        grid_bar(bph);

        // stage 6: h~ gate + GRU update; 32 rows x 64 cols per CTA (all 128 CTAs)
        {
            int row = c * 32 + (tid >> 4);
            int c0  = (tid & 15) * 4;
            u64 acc[2] = {0ull, 0ull};
            row_stream4(Ws, g_hr, g_T1, g_T2, 3, row, c0, acc);
            const float* Xc = Xc_tl + (long)2 * MAT;
            long off = (long)row * 64 + c0;
            float4 xc = *(const float4*)&Xc[off];
            float2 f0 = u2f(acc[0]), f1 = u2f(acc[1]);
            float v0 = f0.x + xc.x, v1 = f0.y + xc.y, v2 = f1.x + xc.z, v3 = f1.y + xc.w;
            float4 hv = *(const float4*)&g_h[off];
            float4 zv = *(const float4*)&g_z[off];
            float4 o;
            o.x = zv.x * hv.x + (1.0f - zv.x) * tanhf(v0);
            o.y = zv.y * hv.y + (1.0f - zv.y) * tanhf(v1);
            o.z = zv.z * hv.z + (1.0f - zv.z) * tanhf(v2);
            o.w = zv.w * hv.w + (1.0f - zv.w) * tanhf(v3);
            *(float4*)&g_h[off] = o;
        }
        grid_bar(bph);
    }

    // ---- Phase E: sp/tp projections (K=64). half = c>>6, 64 rows per CTA ----
    {
        int half = c >> 6;
        load_W(Ws, W1 + (long)half * 4096, 64);
        int row = (c & 63) * 64 + (tid >> 3);
        int c0  = (tid & 7) * 8;
        u64 acc[4] = {0ull,0ull,0ull,0ull};
        row_stream8(Ws, g_h, g_h, g_h, 1, row, c0, acc);
        float* o = half ? g_tp : g_sp;
        long off = (long)row * 64 + c0;
        float2 f0 = u2f(acc[0]), f1 = u2f(acc[1]), f2 = u2f(acc[2]), f3 = u2f(acc[3]);
        float4 v0, v1;
        v0.x = f0.x; v0.y = f0.y; v0.z = f1.x; v0.w = f1.y;
        v1.x = f2.x; v1.y = f2.y; v1.z = f3.x; v1.w = f3.y;
        *(float4*)&o[off] = v0;
        *(float4*)&o[off + 4] = v1;
    }
    grid_bar(bph);

    // ---- Phase F: all-pairs logits. 8b x 8sT x 16tT = 1024 tiles (64x32), 8/CTA ----
    for (int i = 0; i < 8; i++) {
        int unit = c * 8 + i;
        int b  = unit & 7;
        int sT = (unit >> 3) & 7;
        int tT = (unit >> 6) & 15;
        predict_tile(smp, b, sT * 64, tT * 32, b1, W2, b2, out);
    }
}

// ---------------- host: ONE launch ----------------
extern "C" void kernel_launch(void* const* d_in, const int* in_sizes, int n_in,
                              void* d_out, int out_size) {
    const float* x   = (const float*)d_in[0];
    const float* ew  = (const float*)d_in[1];
    const float* Wx  = (const float*)d_in[2];
    const float* bx  = (const float*)d_in[3];
    const float* Wh  = (const float*)d_in[4];
    const float* bh  = (const float*)d_in[5];
    const float* W1  = (const float*)d_in[6];
    const float* b1  = (const float*)d_in[7];
    const float* W2  = (const float*)d_in[8];
    const float* b2  = (const float*)d_in[9];
    const void*  ei  = d_in[10];
    float* out = (float*)d_out;

    cudaFuncSetAttribute(mega_kernel,
                         cudaFuncAttributeMaxDynamicSharedMemorySize,
                         (int)SMEM_BYTES);
    mega_kernel<<<NCTAS, NTHREADS, SMEM_BYTES>>>(x, ew, Wx, bx, Wh, bh,
                                                 W1, b1, W2, b2, ei, out);
}